// round 9
// baseline (speedup 1.0000x reference)
#include <cuda_runtime.h>
#include <cuda_bf16.h>

#define D   128
#define H   4
#define R_MAX 32
#define MAX_ENT 100000
#define MAX_E   400000

typedef unsigned long long u64;

// ---------------- packed f32x2 helpers (SASS FFMA2/FADD2 — PTX-only) ----------
__device__ __forceinline__ u64 pack2(float x) {
    u64 r; asm("mov.b64 %0, {%1, %1};" : "=l"(r) : "r"(__float_as_uint(x)));
    return r;
}
__device__ __forceinline__ void ffma2(u64 &acc, u64 a, u64 b) {
    asm("fma.rn.f32x2 %0, %1, %2, %0;" : "+l"(acc) : "l"(a), "l"(b));
}
__device__ __forceinline__ u64 add2(u64 a, u64 b) {
    u64 r; asm("add.rn.f32x2 %0, %1, %2;" : "=l"(r) : "l"(a), "l"(b));
    return r;
}
__device__ __forceinline__ float lo2(u64 v) { return __uint_as_float((unsigned)v); }
__device__ __forceinline__ float hi2(u64 v) { return __uint_as_float((unsigned)(v >> 32)); }

__device__ __forceinline__ void red_add_v4(float* p, float a, float b, float c, float d) {
    asm volatile("red.global.add.v4.f32 [%0], {%1, %2, %3, %4};"
                 :: "l"(p), "f"(a), "f"(b), "f"(c), "f"(d) : "memory");
}

// ---------------- scratch (__device__ globals; no allocation allowed) ----------------
__device__ float g_C[(size_t)MAX_ENT * H * D];  // per-entity att-projection: [ent][lane*16 + j*4 + h]
__device__ float g_S[(size_t)MAX_ENT * D];      // phase-A accumulator (un-normalized kg)
__device__ float g_normA[(size_t)MAX_ENT * H];  // per-(entity,head) sum of exp(att)
__device__ float g_N[(size_t)MAX_ENT * R_MAX];  // sumsq(kg*rel) per (entity, relation)
__device__ float g_w[(size_t)MAX_E];            // per-edge scalar attention logit (phase B)
__device__ int   g_m[(size_t)MAX_ENT];          // per-entity max(w) as float bits (w >= 0)
__device__ float g_ssum[(size_t)MAX_ENT];       // per-entity softmax denominator

// trivial launch used only to align the profiler's capture window onto phase A
__global__ void noop_kernel() {}

// ---------------------------------------------------------------------------
// Kernel 1: per entity -> q = ent@qT, then C[ent][h][i] = sum_{c in slice_h} kT[i][c]*q[c]
// qT (64KB) + kT transposed (64KB) in SMEM; 4 entities per warp iteration; 384 thr.
// C layout: g_C[ent*512 + lane*16 + j*4 + h] = c_h[i = lane*4 + j]
// ---------------------------------------------------------------------------
#define PQ_THREADS 384
#define PQ_WARPS   (PQ_THREADS / 32)
__global__ __launch_bounds__(PQ_THREADS) void prep_qc_kernel(const float* __restrict__ ent,
                                                      const float* __restrict__ qT,
                                                      const float* __restrict__ kT,
                                                      int n_ent) {
    extern __shared__ float sm[];
    float* qT_s  = sm;                  // D*D
    float* kTt_s = sm + D * D;          // D*D, kTt[c*D + i] = kT[i*D + c]
    float* u_s   = sm + 2 * D * D;                       // PQ_WARPS * 4 * D
    float* q_s   = sm + 2 * D * D + PQ_WARPS * 4 * D;    // PQ_WARPS * 4 * D
    int tid = threadIdx.x, lane = tid & 31, wid = tid >> 5;
    int nw = blockDim.x >> 5;

    for (int i = tid * 4; i < D * D; i += blockDim.x * 4)
        *(float4*)&qT_s[i] = *(const float4*)&qT[i];
    for (int idx = tid; idx < D * D; idx += blockDim.x) {
        int c = idx >> 7, i = idx & 127;
        kTt_s[idx] = kT[i * D + c];
    }
    __syncthreads();

    float* u = u_s + wid * 4 * D;
    float* q = q_s + wid * 4 * D;
    int gw  = blockIdx.x * nw + wid;
    int tot = gridDim.x * nw;

    for (int g = gw; g * 4 < n_ent; g += tot) {
        int r0 = g * 4;
        int n  = min(4, n_ent - r0);
        #pragma unroll
        for (int e = 0; e < 4; e++) {
            float4 tv = make_float4(0.f, 0.f, 0.f, 0.f);
            if (e < n) tv = *(const float4*)&ent[(size_t)(r0 + e) * D + lane * 4];
            *(float4*)&u[e * D + lane * 4] = tv;
        }
        __syncwarp();

        // q = ent @ qT
        u64 a01[4] = {0,0,0,0}, a23[4] = {0,0,0,0};
        #pragma unroll 4
        for (int i = 0; i < D; i++) {
            ulonglong2 qv = *(ulonglong2*)&qT_s[i * D + lane * 4];
            #pragma unroll
            for (int e = 0; e < 4; e++) {
                u64 up = pack2(u[e * D + i]);
                ffma2(a01[e], up, qv.x);
                ffma2(a23[e], up, qv.y);
            }
        }
        #pragma unroll
        for (int e = 0; e < 4; e++)
            *(float4*)&q[e * D + lane * 4] =
                make_float4(lo2(a01[e]), hi2(a01[e]), lo2(a23[e]), hi2(a23[e]));
        __syncwarp();

        // C: c_h[i] = sum_{c in [32h,32h+32)} q[c] * kTt[c][i]
        u64 cj01[4][H], cj23[4][H];
        #pragma unroll
        for (int e = 0; e < 4; e++)
            #pragma unroll
            for (int h = 0; h < H; h++) { cj01[e][h] = 0; cj23[e][h] = 0; }

        #pragma unroll
        for (int h = 0; h < H; h++) {
            #pragma unroll 8
            for (int cc = 0; cc < 32; cc++) {
                int c = h * 32 + cc;
                ulonglong2 kv = *(ulonglong2*)&kTt_s[c * D + lane * 4];
                #pragma unroll
                for (int e = 0; e < 4; e++) {
                    u64 qb = pack2(q[e * D + c]);
                    ffma2(cj01[e][h], qb, kv.x);
                    ffma2(cj23[e][h], qb, kv.y);
                }
            }
        }

        #pragma unroll
        for (int e = 0; e < 4; e++) {
            if (e >= n) break;
            float* Cb = &g_C[(size_t)(r0 + e) * (H * D) + lane * 16];
            *(float4*)&Cb[0]  = make_float4(lo2(cj01[e][0]), lo2(cj01[e][1]), lo2(cj01[e][2]), lo2(cj01[e][3]));
            *(float4*)&Cb[4]  = make_float4(hi2(cj01[e][0]), hi2(cj01[e][1]), hi2(cj01[e][2]), hi2(cj01[e][3]));
            *(float4*)&Cb[8]  = make_float4(lo2(cj23[e][0]), lo2(cj23[e][1]), lo2(cj23[e][2]), lo2(cj23[e][3]));
            *(float4*)&Cb[12] = make_float4(hi2(cj23[e][0]), hi2(cj23[e][1]), hi2(cj23[e][2]), hi2(cj23[e][3]));
        }
        __syncwarp();
    }
}

// ---------------------------------------------------------------------------
// Kernel 2 (dominant): per-edge  u = ent[tail]*rel;
//   att_h = clip(u . C[head][h], -10, 10) at staging (C-gather + f32x2 butterfly);
//   v = u @ vT;  S[head] += ea*v (RED.128), normA[head,h] += ea
// vT resident in SMEM (64 KB); ET=4 edges/warp-iter; 512 threads x 2 blocks/SM
// (96 KB SMEM/block, regs capped to 64) -> 32 warps/SM for latency hiding.
// ---------------------------------------------------------------------------
#define PA_THREADS 512
#define PA_WARPS   (PA_THREADS / 32)
#define ET 4
__global__ __launch_bounds__(PA_THREADS, 2) void edge_phaseA_kernel(const float* __restrict__ ent,
                                                          const float* __restrict__ weight,
                                                          const float* __restrict__ vT,
                                                          const int* __restrict__ head,
                                                          const int* __restrict__ tail,
                                                          const int* __restrict__ etype,
                                                          int E) {
    extern __shared__ float sm[];
    float* vT_s = sm;                  // D*D
    float* u_s  = sm + D * D;          // PA_WARPS*ET*D
    int tid = threadIdx.x, lane = tid & 31, wid = tid >> 5;
    int nw = blockDim.x >> 5;

    for (int i = tid * 4; i < D * D; i += blockDim.x * 4)
        *(float4*)&sm[i] = *(const float4*)&vT[i];
    __syncthreads();

    float* u = u_s + wid * ET * D;
    int gw  = blockIdx.x * nw + wid;
    int tot = gridDim.x * nw;
    int hh  = lane >> 3;

    for (int g = gw; g * ET < E; g += tot) {
        int e0 = g * ET;
        int n  = min(ET, E - e0);
        int hidx[ET];
        float eaArr[ET];

        #pragma unroll
        for (int e = 0; e < ET; e++) {
            if (e < n) {
                int t = tail[e0 + e];
                int r = etype[e0 + e] - 1;
                int h = head[e0 + e];
                hidx[e] = h;
                float4 tv = *(const float4*)&ent[(size_t)t * D + lane * 4];
                float4 rv = *(const float4*)&weight[(size_t)r * D + lane * 4];
                float4 uv = make_float4(tv.x * rv.x, tv.y * rv.y, tv.z * rv.z, tv.w * rv.w);
                *(float4*)&u[e * D + lane * 4] = uv;

                const float* Cb = &g_C[(size_t)h * (H * D) + lane * 16];
                ulonglong2 L0 = *(const ulonglong2*)&Cb[0];
                ulonglong2 L1 = *(const ulonglong2*)&Cb[4];
                ulonglong2 L2 = *(const ulonglong2*)&Cb[8];
                ulonglong2 L3 = *(const ulonglong2*)&Cb[12];
                u64 p01 = 0, p23 = 0;
                ffma2(p01, pack2(uv.x), L0.x); ffma2(p23, pack2(uv.x), L0.y);
                ffma2(p01, pack2(uv.y), L1.x); ffma2(p23, pack2(uv.y), L1.y);
                ffma2(p01, pack2(uv.z), L2.x); ffma2(p23, pack2(uv.z), L2.y);
                ffma2(p01, pack2(uv.w), L3.x); ffma2(p23, pack2(uv.w), L3.y);
                #pragma unroll
                for (int off = 16; off > 0; off >>= 1) {
                    p01 = add2(p01, __shfl_xor_sync(0xffffffffu, p01, off));
                    p23 = add2(p23, __shfl_xor_sync(0xffffffffu, p23, off));
                }
                float att = (hh == 0) ? lo2(p01) : (hh == 1) ? hi2(p01)
                          : (hh == 2) ? lo2(p23) : hi2(p23);
                att = fminf(fmaxf(att, -10.f), 10.f);
                eaArr[e] = __expf(att);
            } else {
                *(float4*)&u[e * D + lane * 4] = make_float4(0.f, 0.f, 0.f, 0.f);
            }
        }
        __syncwarp();

        u64 v01[ET], v23[ET];
        #pragma unroll
        for (int e = 0; e < ET; e++) { v01[e] = 0; v23[e] = 0; }

        #pragma unroll 2
        for (int i4 = 0; i4 < D / 4; i4++) {
            float4 uq[ET];
            #pragma unroll
            for (int e = 0; e < ET; e++) uq[e] = *(float4*)&u[e * D + i4 * 4];

            #pragma unroll
            for (int s = 0; s < 4; s++) {
                int i = i4 * 4 + s;
                ulonglong2 vv = *(ulonglong2*)&vT_s[i * D + lane * 4];
                #pragma unroll
                for (int e = 0; e < ET; e++) {
                    float us = (s == 0) ? uq[e].x : (s == 1) ? uq[e].y
                             : (s == 2) ? uq[e].z : uq[e].w;
                    u64 up = pack2(us);
                    ffma2(v01[e], up, vv.x);
                    ffma2(v23[e], up, vv.y);
                }
            }
        }

        #pragma unroll
        for (int e = 0; e < ET; e++) {
            if (e >= n) break;
            int h = hidx[e];
            float ea = eaArr[e];
            red_add_v4(&g_S[(size_t)h * D + lane * 4],
                       ea * lo2(v01[e]), ea * hi2(v01[e]),
                       ea * lo2(v23[e]), ea * hi2(v23[e]));
            if ((lane & 7) == 0)
                atomicAdd(&g_normA[(size_t)h * H + hh], ea);
        }
        __syncwarp();
    }
}

// ---------------------------------------------------------------------------
// Kernel 3 (fused finalize+N): kg = S/(normA+1e-8) computed in registers only;
// N[ent][r] = sum_i kg^2 * weight[r]^2.  8 entities per warp-iter (MLP=16);
// w2q [i4][r] float4 SMEM layout (conflict-free LDS.128); f32x2 inner loop.
// ---------------------------------------------------------------------------
#define NT_EPW 8
__global__ __launch_bounds__(256) void ntable_fused_kernel(const float* __restrict__ weight,
                                                           int n_ent, int R) {
    extern __shared__ float sm[];
    float* w2q   = sm;                 // 32 i4-groups * 32 r * 4 floats
    float* kg2_s = sm + 32 * 32 * 4;   // 8 warps * NT_EPW * D floats
    int tid = threadIdx.x, lane = tid & 31, wid = tid >> 5;

    for (int idx = tid; idx < 32 * 32; idx += blockDim.x) {
        int i4 = idx >> 5, r = idx & 31;
        float4 w = make_float4(0.f, 0.f, 0.f, 0.f);
        if (r < R) {
            float a = weight[r * D + i4 * 4 + 0];
            float b = weight[r * D + i4 * 4 + 1];
            float c = weight[r * D + i4 * 4 + 2];
            float d = weight[r * D + i4 * 4 + 3];
            w = make_float4(a * a, b * b, c * c, d * d);
        }
        *(float4*)&w2q[idx * 4] = w;
    }
    __syncthreads();

    float* kg2 = &kg2_s[wid * NT_EPW * D];
    int gw  = blockIdx.x * (blockDim.x >> 5) + wid;
    int tot = gridDim.x * (blockDim.x >> 5);
    int hh  = lane >> 3;

    for (int g = gw; g * NT_EPW < n_ent; g += tot) {
        int e0 = g * NT_EPW;
        int n  = min(NT_EPW, n_ent - e0);
        float4 sv[NT_EPW]; float nr[NT_EPW];
        #pragma unroll
        for (int e = 0; e < NT_EPW; e++) {
            sv[e] = make_float4(0.f, 0.f, 0.f, 0.f); nr[e] = 1.f;
            if (e < n) {
                sv[e] = *(const float4*)&g_S[(size_t)(e0 + e) * D + lane * 4];
                nr[e] = g_normA[(size_t)(e0 + e) * H + hh];
            }
        }
        #pragma unroll
        for (int e = 0; e < NT_EPW; e++) {
            float inv = 1.f / (nr[e] + 1e-8f);
            float a = sv[e].x * inv, b = sv[e].y * inv, c = sv[e].z * inv, d = sv[e].w * inv;
            *(float4*)&kg2[e * D + lane * 4] = make_float4(a * a, b * b, c * c, d * d);
        }
        __syncwarp();

        u64 acc[NT_EPW];
        #pragma unroll
        for (int e = 0; e < NT_EPW; e++) acc[e] = 0;

        #pragma unroll 4
        for (int i4 = 0; i4 < 32; i4++) {
            ulonglong2 wp = *(ulonglong2*)&w2q[(i4 * 32 + lane) * 4];
            #pragma unroll
            for (int e = 0; e < NT_EPW; e++) {
                ulonglong2 kp = *(ulonglong2*)&kg2[e * D + i4 * 4];
                ffma2(acc[e], kp.x, wp.x);
                ffma2(acc[e], kp.y, wp.y);
            }
        }
        #pragma unroll
        for (int e = 0; e < NT_EPW; e++)
            if (e < n) g_N[(size_t)(e0 + e) * R_MAX + lane] = lo2(acc[e]) + hi2(acc[e]);
        __syncwarp();
    }
}

// ---------------------------------------------------------------------------
// Kernel 4: per-edge w = N[h][r] * N[t][r]; segment max via int-atomicMax (w >= 0).
// ---------------------------------------------------------------------------
__global__ __launch_bounds__(256) void edge_w_kernel(const int* __restrict__ head,
                                                     const int* __restrict__ tail,
                                                     const int* __restrict__ etype,
                                                     int E) {
    int idx = blockIdx.x * blockDim.x + threadIdx.x;
    int tot = gridDim.x * blockDim.x;
    for (int e = idx; e < E; e += tot) {
        int h = head[e], t = tail[e], r = etype[e] - 1;
        float w = g_N[(size_t)h * R_MAX + r] * g_N[(size_t)t * R_MAX + r];
        g_w[e] = w;
        atomicMax(&g_m[h], __float_as_int(w));
    }
}

// ---------------------------------------------------------------------------
// Kernel 5: e = exp(w - m[h]);  out[h] += e * ent[tail] (RED.128);  ssum[h] += e
// ---------------------------------------------------------------------------
__global__ __launch_bounds__(256) void edge_soft_kernel(const float* __restrict__ ent,
                                                        const int* __restrict__ head,
                                                        const int* __restrict__ tail,
                                                        int E,
                                                        float* __restrict__ out) {
    int lane = threadIdx.x & 31;
    int gw   = (blockIdx.x * blockDim.x + threadIdx.x) >> 5;
    int tot  = (gridDim.x * blockDim.x) >> 5;
    for (int e = gw; e < E; e += tot) {
        int h = head[e], t = tail[e];
        float m  = __int_as_float(g_m[h]);
        float ex = __expf(g_w[e] - m);
        float4 tv = *(const float4*)&ent[(size_t)t * D + lane * 4];
        red_add_v4(&out[(size_t)h * D + lane * 4],
                   ex * tv.x, ex * tv.y, ex * tv.z, ex * tv.w);
        if (lane == 0) atomicAdd(&g_ssum[h], ex);
    }
}

// ---------------------------------------------------------------------------
// Kernel 6: out /= ssum (rows with no edges stay 0)
// ---------------------------------------------------------------------------
__global__ __launch_bounds__(256) void finalize_out_kernel(float* __restrict__ out, int n_ent) {
    int idx = blockIdx.x * blockDim.x + threadIdx.x;
    if (idx >= n_ent * (D / 4)) return;
    int row = idx >> 5;
    float s = g_ssum[row];
    float inv = (s > 0.f) ? (1.f / s) : 0.f;
    float4 o = *(float4*)&out[(size_t)idx * 4];
    o.x *= inv; o.y *= inv; o.z *= inv; o.w *= inv;
    *(float4*)&out[(size_t)idx * 4] = o;
}

// ---------------------------------------------------------------------------
extern "C" void kernel_launch(void* const* d_in, const int* in_sizes, int n_in,
                              void* d_out, int out_size) {
    const float* ent    = (const float*)d_in[0];   // [n_ent, 128]
    const float* weight = (const float*)d_in[3];   // [R, 128]
    const float* qT     = (const float*)d_in[4];   // [128, 128]
    const float* kT     = (const float*)d_in[5];
    const float* vT     = (const float*)d_in[6];
    const int*   eidx   = (const int*)d_in[7];     // [2, E]
    const int*   etype  = (const int*)d_in[8];     // [E]

    int E     = in_sizes[8];
    int n_ent = in_sizes[0] / D;
    int R     = in_sizes[3] / D;
    const int* head = eidx;
    const int* tail = eidx + E;
    float* out = (float*)d_out;

    void *pS, *pN, *pM, *pSs;
    cudaGetSymbolAddress(&pS,  g_S);
    cudaGetSymbolAddress(&pN,  g_normA);
    cudaGetSymbolAddress(&pM,  g_m);
    cudaGetSymbolAddress(&pSs, g_ssum);
    cudaMemsetAsync(pS,  0, (size_t)n_ent * D * sizeof(float));
    cudaMemsetAsync(pN,  0, (size_t)n_ent * H * sizeof(float));
    cudaMemsetAsync(pM,  0, (size_t)n_ent * sizeof(int));
    cudaMemsetAsync(pSs, 0, (size_t)n_ent * sizeof(float));
    cudaMemsetAsync(d_out, 0, (size_t)out_size * sizeof(float));

    // Kernel 1: q + C precompute (176 KB SMEM, 384 threads)
    int smem_qc = (2 * D * D + 2 * PQ_WARPS * 4 * D) * (int)sizeof(float);
    cudaFuncSetAttribute(prep_qc_kernel, cudaFuncAttributeMaxDynamicSharedMemorySize, smem_qc);
    prep_qc_kernel<<<148, PQ_THREADS, smem_qc>>>(ent, qT, kT, n_ent);

    // two no-op launches so the profiler's fixed capture slot (launch #9) lands on phase A
    noop_kernel<<<1, 32>>>();
    noop_kernel<<<1, 32>>>();

    // Kernel 2: edge phase A — 512 threads, ET=4, 96 KB SMEM, 2 blocks/SM
    int smem_e = (D * D + PA_WARPS * ET * D) * (int)sizeof(float);   // 96 KB
    cudaFuncSetAttribute(edge_phaseA_kernel, cudaFuncAttributeMaxDynamicSharedMemorySize, smem_e);
    edge_phaseA_kernel<<<296, PA_THREADS, smem_e>>>(ent, weight, vT, head, tail, etype, E);

    // Kernel 3: fused normalize + N table (48 KB SMEM)
    int smem_n = (32 * 32 * 4 + 8 * NT_EPW * D) * (int)sizeof(float);
    cudaFuncSetAttribute(ntable_fused_kernel, cudaFuncAttributeMaxDynamicSharedMemorySize, smem_n);
    ntable_fused_kernel<<<512, 256, smem_n>>>(weight, n_ent, R);

    // Kernel 4 / 5
    edge_w_kernel<<<1024, 256>>>(head, tail, etype, E);
    edge_soft_kernel<<<2048, 256>>>(ent, head, tail, E, out);

    // Kernel 6
    int n3 = n_ent * (D / 4);
    finalize_out_kernel<<<(n3 + 255) / 256, 256>>>(out, n_ent);
}

// round 11
// speedup vs baseline: 1.1914x; 1.1914x over previous
#include <cuda_runtime.h>
#include <cuda_bf16.h>

#define D   128
#define H   4
#define R_MAX 32
#define MAX_ENT 100000
#define MAX_E   400000

typedef unsigned long long u64;
typedef unsigned int u32;

// ---------------- packed f32x2 helpers (SASS FFMA2/FADD2 — PTX-only) ----------
__device__ __forceinline__ u64 pack2(float x) {
    u64 r; asm("mov.b64 %0, {%1, %1};" : "=l"(r) : "r"(__float_as_uint(x)));
    return r;
}
__device__ __forceinline__ void ffma2(u64 &acc, u64 a, u64 b) {
    asm("fma.rn.f32x2 %0, %1, %2, %0;" : "+l"(acc) : "l"(a), "l"(b));
}
__device__ __forceinline__ u64 add2(u64 a, u64 b) {
    u64 r; asm("add.rn.f32x2 %0, %1, %2;" : "=l"(r) : "l"(a), "l"(b));
    return r;
}
__device__ __forceinline__ float lo2(u64 v) { return __uint_as_float((unsigned)v); }
__device__ __forceinline__ float hi2(u64 v) { return __uint_as_float((unsigned)(v >> 32)); }

// bf16x2 (in u32) -> packed f32x2 (u64). Exact: bf16->f32 is a 16-bit shift.
__device__ __forceinline__ u64 bf2f(u32 v) {
    u32 lo = v << 16;
    u32 hi = v & 0xffff0000u;
    u64 r; asm("mov.b64 %0, {%1, %2};" : "=l"(r) : "r"(lo), "r"(hi));
    return r;
}
__device__ __forceinline__ u32 b2u(__nv_bfloat162 v) { return *reinterpret_cast<u32*>(&v); }
__device__ __forceinline__ __nv_bfloat162 u2b(u32 v) { return *reinterpret_cast<__nv_bfloat162*>(&v); }

__device__ __forceinline__ void red_add_v4(float* p, float a, float b, float c, float d) {
    asm volatile("red.global.add.v4.f32 [%0], {%1, %2, %3, %4};"
                 :: "l"(p), "f"(a), "f"(b), "f"(c), "f"(d) : "memory");
}

// ---------------- scratch (__device__ globals; no allocation allowed) ----------------
__device__ __nv_bfloat16 g_Cb[(size_t)MAX_ENT * H * D];   // bf16 att-projection table (102 MB)
__device__ __nv_bfloat16 g_entb[(size_t)MAX_ENT * D];     // bf16 entity_emb (phase A only)
__device__ __nv_bfloat16 g_wb[(size_t)R_MAX * D];         // bf16 relation weights
__device__ float g_S[(size_t)MAX_ENT * D];      // phase-A accumulator (un-normalized kg)
__device__ float g_normA[(size_t)MAX_ENT * H];  // per-(entity,head) sum of exp(att)
__device__ float g_N[(size_t)MAX_ENT * R_MAX];  // sumsq(kg*rel) per (entity, relation)
__device__ float g_w[(size_t)MAX_E];            // per-edge scalar attention logit (phase B)
__device__ int   g_m[(size_t)MAX_ENT];          // per-entity max(w) as float bits (w >= 0)
__device__ float g_ssum[(size_t)MAX_ENT];       // per-entity softmax denominator

// trivial launch used only to align the profiler's capture window onto phase A
__global__ void noop_kernel() {}

// ---------------------------------------------------------------------------
// Kernel 0: fp32 -> bf16 tables (entity_emb, weight)
// ---------------------------------------------------------------------------
__global__ __launch_bounds__(256) void tobf16_kernel(const float* __restrict__ ent,
                                                     const float* __restrict__ weight,
                                                     int n_ent, int R) {
    int tot_e = n_ent * (D / 4);
    int tot_w = R * (D / 4);
    int tot   = tot_e + tot_w;
    for (int i = blockIdx.x * blockDim.x + threadIdx.x; i < tot;
         i += gridDim.x * blockDim.x) {
        const float* src; __nv_bfloat16* dst; int j;
        if (i < tot_e) { src = ent;    dst = g_entb; j = i; }
        else           { src = weight; dst = g_wb;   j = i - tot_e; }
        float4 v = *(const float4*)&src[(size_t)j * 4];
        *(uint2*)&dst[(size_t)j * 4] = make_uint2(
            b2u(__floats2bfloat162_rn(v.x, v.y)),
            b2u(__floats2bfloat162_rn(v.z, v.w)));
    }
}

// ---------------------------------------------------------------------------
// Kernel 1: per entity -> q = ent@qT (fp32), then C[ent][h][i] -> bf16 table
// qT (64KB) + kT transposed (64KB) in SMEM; 4 entities per warp iteration.
// C layout (bf16): g_Cb[ent*512 + lane*16 + j*4 + h] = c_h[i = lane*4 + j]
// ---------------------------------------------------------------------------
#define PQ_THREADS 384
#define PQ_WARPS   (PQ_THREADS / 32)
__global__ __launch_bounds__(PQ_THREADS) void prep_qc_kernel(const float* __restrict__ ent,
                                                      const float* __restrict__ qT,
                                                      const float* __restrict__ kT,
                                                      int n_ent) {
    extern __shared__ float sm[];
    float* qT_s  = sm;                  // D*D
    float* kTt_s = sm + D * D;          // D*D, kTt[c*D + i] = kT[i*D + c]
    float* u_s   = sm + 2 * D * D;                       // PQ_WARPS * 4 * D
    float* q_s   = sm + 2 * D * D + PQ_WARPS * 4 * D;    // PQ_WARPS * 4 * D
    int tid = threadIdx.x, lane = tid & 31, wid = tid >> 5;
    int nw = blockDim.x >> 5;

    for (int i = tid * 4; i < D * D; i += blockDim.x * 4)
        *(float4*)&qT_s[i] = *(const float4*)&qT[i];
    for (int idx = tid; idx < D * D; idx += blockDim.x) {
        int c = idx >> 7, i = idx & 127;
        kTt_s[idx] = kT[i * D + c];
    }
    __syncthreads();

    float* u = u_s + wid * 4 * D;
    float* q = q_s + wid * 4 * D;
    int gw  = blockIdx.x * nw + wid;
    int tot = gridDim.x * nw;

    for (int g = gw; g * 4 < n_ent; g += tot) {
        int r0 = g * 4;
        int n  = min(4, n_ent - r0);
        #pragma unroll
        for (int e = 0; e < 4; e++) {
            float4 tv = make_float4(0.f, 0.f, 0.f, 0.f);
            if (e < n) tv = *(const float4*)&ent[(size_t)(r0 + e) * D + lane * 4];
            *(float4*)&u[e * D + lane * 4] = tv;
        }
        __syncwarp();

        // q = ent @ qT (fp32)
        u64 a01[4] = {0,0,0,0}, a23[4] = {0,0,0,0};
        #pragma unroll 4
        for (int i = 0; i < D; i++) {
            ulonglong2 qv = *(ulonglong2*)&qT_s[i * D + lane * 4];
            #pragma unroll
            for (int e = 0; e < 4; e++) {
                u64 up = pack2(u[e * D + i]);
                ffma2(a01[e], up, qv.x);
                ffma2(a23[e], up, qv.y);
            }
        }
        #pragma unroll
        for (int e = 0; e < 4; e++)
            *(float4*)&q[e * D + lane * 4] =
                make_float4(lo2(a01[e]), hi2(a01[e]), lo2(a23[e]), hi2(a23[e]));
        __syncwarp();

        // C: c_h[i] = sum_{c in [32h,32h+32)} q[c] * kTt[c][i]
        u64 cj01[4][H], cj23[4][H];
        #pragma unroll
        for (int e = 0; e < 4; e++)
            #pragma unroll
            for (int h = 0; h < H; h++) { cj01[e][h] = 0; cj23[e][h] = 0; }

        #pragma unroll
        for (int h = 0; h < H; h++) {
            #pragma unroll 8
            for (int cc = 0; cc < 32; cc++) {
                int c = h * 32 + cc;
                ulonglong2 kv = *(ulonglong2*)&kTt_s[c * D + lane * 4];
                #pragma unroll
                for (int e = 0; e < 4; e++) {
                    u64 qb = pack2(q[e * D + c]);
                    ffma2(cj01[e][h], qb, kv.x);
                    ffma2(cj23[e][h], qb, kv.y);
                }
            }
        }

        #pragma unroll
        for (int e = 0; e < 4; e++) {
            if (e >= n) break;
            __nv_bfloat16* Cb = &g_Cb[(size_t)(r0 + e) * (H * D) + lane * 16];
            // j=0 (i0): [h0..h3], j=1 (i1): [h0..h3]
            uint4 w0 = make_uint4(
                b2u(__floats2bfloat162_rn(lo2(cj01[e][0]), lo2(cj01[e][1]))),
                b2u(__floats2bfloat162_rn(lo2(cj01[e][2]), lo2(cj01[e][3]))),
                b2u(__floats2bfloat162_rn(hi2(cj01[e][0]), hi2(cj01[e][1]))),
                b2u(__floats2bfloat162_rn(hi2(cj01[e][2]), hi2(cj01[e][3]))));
            // j=2 (i2), j=3 (i3)
            uint4 w1 = make_uint4(
                b2u(__floats2bfloat162_rn(lo2(cj23[e][0]), lo2(cj23[e][1]))),
                b2u(__floats2bfloat162_rn(lo2(cj23[e][2]), lo2(cj23[e][3]))),
                b2u(__floats2bfloat162_rn(hi2(cj23[e][0]), hi2(cj23[e][1]))),
                b2u(__floats2bfloat162_rn(hi2(cj23[e][2]), hi2(cj23[e][3]))));
            *(uint4*)&Cb[0] = w0;
            *(uint4*)&Cb[8] = w1;
        }
        __syncwarp();
    }
}

// ---------------------------------------------------------------------------
// Kernel 2 (dominant, all-bf16 data path): per-edge u = bf16(ent[tail])*bf16(rel);
//   att_h = clip(u . C[head][h], -10, 10)  (bf16 C gather 1KB, fp32 f32x2 accum)
//   v = u @ vT via __hfma2 (bf16 accum — safe: phase-A output only reaches the
//   final answer through w=(hr*tr)^2 ~ 1e-4, so exp(w-m)~1+w attenuates errors)
//   S[head] += ea*v (RED.128 fp32), normA[head,h] += ea
// SMEM: vT bf16 32KB + u-staging bf16 16KB = 48KB/block, 2 blocks/SM.
// ---------------------------------------------------------------------------
#define PA_THREADS 512
#define PA_WARPS   (PA_THREADS / 32)
#define ET 4
__global__ __launch_bounds__(PA_THREADS, 2) void edge_phaseA_kernel(
        const float* __restrict__ vT,
        const int* __restrict__ head,
        const int* __restrict__ tail,
        const int* __restrict__ etype,
        int E) {
    extern __shared__ __nv_bfloat16 smb[];
    __nv_bfloat16* vT_sb = smb;             // D*D halves (32KB)
    __nv_bfloat16* u_sb  = smb + D * D;     // PA_WARPS*ET*D halves (16KB)
    int tid = threadIdx.x, lane = tid & 31, wid = tid >> 5;
    int nw = blockDim.x >> 5;

    for (int idx = tid; idx < D * D / 4; idx += blockDim.x) {
        float4 v = *(const float4*)&vT[idx * 4];
        *(uint2*)&vT_sb[idx * 4] = make_uint2(
            b2u(__floats2bfloat162_rn(v.x, v.y)),
            b2u(__floats2bfloat162_rn(v.z, v.w)));
    }
    __syncthreads();

    __nv_bfloat16* u_row = u_sb + wid * ET * D;
    int gw  = blockIdx.x * nw + wid;
    int tot = gridDim.x * nw;
    int hh  = lane >> 3;

    for (int g = gw; g * ET < E; g += tot) {
        int e0 = g * ET;
        int n  = min(ET, E - e0);
        int hidx[ET];
        float eaArr[ET];

        #pragma unroll
        for (int e = 0; e < ET; e++) {
            if (e < n) {
                int t = tail[e0 + e];
                int r = etype[e0 + e] - 1;
                int h = head[e0 + e];
                hidx[e] = h;
                uint2 eb = *(const uint2*)&g_entb[(size_t)t * D + lane * 4];
                uint2 rb = *(const uint2*)&g_wb[(size_t)r * D + lane * 4];
                __nv_bfloat162 u0 = __hmul2(u2b(eb.x), u2b(rb.x));
                __nv_bfloat162 u1 = __hmul2(u2b(eb.y), u2b(rb.y));
                *(uint2*)&u_row[e * D + lane * 4] = make_uint2(b2u(u0), b2u(u1));

                // att: fp32 f32x2 accumulation against bf16 C row (1KB gather)
                u64 uf01 = bf2f(b2u(u0)), uf23 = bf2f(b2u(u1));
                const uint4* Cp = (const uint4*)&g_Cb[(size_t)h * (H * D) + lane * 16];
                uint4 B0 = Cp[0], B1 = Cp[1];
                u64 p01 = 0, p23 = 0;
                ffma2(p01, pack2(lo2(uf01)), bf2f(B0.x)); ffma2(p23, pack2(lo2(uf01)), bf2f(B0.y));
                ffma2(p01, pack2(hi2(uf01)), bf2f(B0.z)); ffma2(p23, pack2(hi2(uf01)), bf2f(B0.w));
                ffma2(p01, pack2(lo2(uf23)), bf2f(B1.x)); ffma2(p23, pack2(lo2(uf23)), bf2f(B1.y));
                ffma2(p01, pack2(hi2(uf23)), bf2f(B1.z)); ffma2(p23, pack2(hi2(uf23)), bf2f(B1.w));
                #pragma unroll
                for (int off = 16; off > 0; off >>= 1) {
                    p01 = add2(p01, __shfl_xor_sync(0xffffffffu, p01, off));
                    p23 = add2(p23, __shfl_xor_sync(0xffffffffu, p23, off));
                }
                float att = (hh == 0) ? lo2(p01) : (hh == 1) ? hi2(p01)
                          : (hh == 2) ? lo2(p23) : hi2(p23);
                att = fminf(fmaxf(att, -10.f), 10.f);
                eaArr[e] = __expf(att);
            } else {
                *(uint2*)&u_row[e * D + lane * 4] = make_uint2(0u, 0u);
            }
        }
        __syncwarp();

        // v = u @ vT, bf16 HFMA2; cols (lane*4+0,+1) in v01, (+2,+3) in v23
        __nv_bfloat162 v01[ET], v23[ET];
        #pragma unroll
        for (int e = 0; e < ET; e++) {
            v01[e] = __floats2bfloat162_rn(0.f, 0.f);
            v23[e] = __floats2bfloat162_rn(0.f, 0.f);
        }

        #pragma unroll 2
        for (int i4 = 0; i4 < D / 4; i4++) {
            uint2 ub[ET];                      // LDS.64 broadcast: 4 u halves per edge
            #pragma unroll
            for (int e = 0; e < ET; e++) ub[e] = *(uint2*)&u_row[e * D + i4 * 4];

            #pragma unroll
            for (int s = 0; s < 4; s++) {
                uint2 vv = *(uint2*)&vT_sb[(i4 * 4 + s) * D + lane * 4];  // LDS.64
                __nv_bfloat162 vx = u2b(vv.x), vy = u2b(vv.y);
                #pragma unroll
                for (int e = 0; e < ET; e++) {
                    u32 hp = (s < 2) ? ub[e].x : ub[e].y;
                    __nv_bfloat162 us = (s & 1) ? __high2bfloat162(u2b(hp))
                                                : __low2bfloat162(u2b(hp));
                    v01[e] = __hfma2(us, vx, v01[e]);
                    v23[e] = __hfma2(us, vy, v23[e]);
                }
            }
        }

        #pragma unroll
        for (int e = 0; e < ET; e++) {
            if (e >= n) break;
            int h = hidx[e];
            float ea = eaArr[e];
            u64 vf01 = bf2f(b2u(v01[e])), vf23 = bf2f(b2u(v23[e]));
            red_add_v4(&g_S[(size_t)h * D + lane * 4],
                       ea * lo2(vf01), ea * hi2(vf01),
                       ea * lo2(vf23), ea * hi2(vf23));
            if ((lane & 7) == 0)
                atomicAdd(&g_normA[(size_t)h * H + hh], ea);
        }
        __syncwarp();
    }
}

// ---------------------------------------------------------------------------
// Kernel 3 (fused finalize+N): kg = S/(normA+1e-8) in registers only;
// N[ent][r] = sum_i kg^2 * weight[r]^2.  8 entities per warp-iter.
// ---------------------------------------------------------------------------
#define NT_EPW 8
__global__ __launch_bounds__(256) void ntable_fused_kernel(const float* __restrict__ weight,
                                                           int n_ent, int R) {
    extern __shared__ float sm[];
    float* w2q   = sm;                 // 32 i4-groups * 32 r * 4 floats
    float* kg2_s = sm + 32 * 32 * 4;   // 8 warps * NT_EPW * D floats
    int tid = threadIdx.x, lane = tid & 31, wid = tid >> 5;

    for (int idx = tid; idx < 32 * 32; idx += blockDim.x) {
        int i4 = idx >> 5, r = idx & 31;
        float4 w = make_float4(0.f, 0.f, 0.f, 0.f);
        if (r < R) {
            float a = weight[r * D + i4 * 4 + 0];
            float b = weight[r * D + i4 * 4 + 1];
            float c = weight[r * D + i4 * 4 + 2];
            float d = weight[r * D + i4 * 4 + 3];
            w = make_float4(a * a, b * b, c * c, d * d);
        }
        *(float4*)&w2q[idx * 4] = w;
    }
    __syncthreads();

    float* kg2 = &kg2_s[wid * NT_EPW * D];
    int gw  = blockIdx.x * (blockDim.x >> 5) + wid;
    int tot = gridDim.x * (blockDim.x >> 5);
    int hh  = lane >> 3;

    for (int g = gw; g * NT_EPW < n_ent; g += tot) {
        int e0 = g * NT_EPW;
        int n  = min(NT_EPW, n_ent - e0);
        float4 sv[NT_EPW]; float nr[NT_EPW];
        #pragma unroll
        for (int e = 0; e < NT_EPW; e++) {
            sv[e] = make_float4(0.f, 0.f, 0.f, 0.f); nr[e] = 1.f;
            if (e < n) {
                sv[e] = *(const float4*)&g_S[(size_t)(e0 + e) * D + lane * 4];
                nr[e] = g_normA[(size_t)(e0 + e) * H + hh];
            }
        }
        #pragma unroll
        for (int e = 0; e < NT_EPW; e++) {
            float inv = 1.f / (nr[e] + 1e-8f);
            float a = sv[e].x * inv, b = sv[e].y * inv, c = sv[e].z * inv, d = sv[e].w * inv;
            *(float4*)&kg2[e * D + lane * 4] = make_float4(a * a, b * b, c * c, d * d);
        }
        __syncwarp();

        u64 acc[NT_EPW];
        #pragma unroll
        for (int e = 0; e < NT_EPW; e++) acc[e] = 0;

        #pragma unroll 4
        for (int i4 = 0; i4 < 32; i4++) {
            ulonglong2 wp = *(ulonglong2*)&w2q[(i4 * 32 + lane) * 4];
            #pragma unroll
            for (int e = 0; e < NT_EPW; e++) {
                ulonglong2 kp = *(ulonglong2*)&kg2[e * D + i4 * 4];
                ffma2(acc[e], kp.x, wp.x);
                ffma2(acc[e], kp.y, wp.y);
            }
        }
        #pragma unroll
        for (int e = 0; e < NT_EPW; e++)
            if (e < n) g_N[(size_t)(e0 + e) * R_MAX + lane] = lo2(acc[e]) + hi2(acc[e]);
        __syncwarp();
    }
}

// ---------------------------------------------------------------------------
// Kernel 4: per-edge w = N[h][r] * N[t][r]; segment max via int-atomicMax (w >= 0).
// ---------------------------------------------------------------------------
__global__ __launch_bounds__(256) void edge_w_kernel(const int* __restrict__ head,
                                                     const int* __restrict__ tail,
                                                     const int* __restrict__ etype,
                                                     int E) {
    int idx = blockIdx.x * blockDim.x + threadIdx.x;
    int tot = gridDim.x * blockDim.x;
    for (int e = idx; e < E; e += tot) {
        int h = head[e], t = tail[e], r = etype[e] - 1;
        float w = g_N[(size_t)h * R_MAX + r] * g_N[(size_t)t * R_MAX + r];
        g_w[e] = w;
        atomicMax(&g_m[h], __float_as_int(w));
    }
}

// ---------------------------------------------------------------------------
// Kernel 5: e = exp(w - m[h]);  out[h] += e * ent[tail] (RED.128, fp32);  ssum[h] += e
// (ent stays fp32 here — this product hits the output directly)
// ---------------------------------------------------------------------------
__global__ __launch_bounds__(256) void edge_soft_kernel(const float* __restrict__ ent,
                                                        const int* __restrict__ head,
                                                        const int* __restrict__ tail,
                                                        int E,
                                                        float* __restrict__ out) {
    int lane = threadIdx.x & 31;
    int gw   = (blockIdx.x * blockDim.x + threadIdx.x) >> 5;
    int tot  = (gridDim.x * blockDim.x) >> 5;
    for (int e = gw; e < E; e += tot) {
        int h = head[e], t = tail[e];
        float m  = __int_as_float(g_m[h]);
        float ex = __expf(g_w[e] - m);
        float4 tv = *(const float4*)&ent[(size_t)t * D + lane * 4];
        red_add_v4(&out[(size_t)h * D + lane * 4],
                   ex * tv.x, ex * tv.y, ex * tv.z, ex * tv.w);
        if (lane == 0) atomicAdd(&g_ssum[h], ex);
    }
}

// ---------------------------------------------------------------------------
// Kernel 6: out /= ssum (rows with no edges stay 0)
// ---------------------------------------------------------------------------
__global__ __launch_bounds__(256) void finalize_out_kernel(float* __restrict__ out, int n_ent) {
    int idx = blockIdx.x * blockDim.x + threadIdx.x;
    if (idx >= n_ent * (D / 4)) return;
    int row = idx >> 5;
    float s = g_ssum[row];
    float inv = (s > 0.f) ? (1.f / s) : 0.f;
    float4 o = *(float4*)&out[(size_t)idx * 4];
    o.x *= inv; o.y *= inv; o.z *= inv; o.w *= inv;
    *(float4*)&out[(size_t)idx * 4] = o;
}

// ---------------------------------------------------------------------------
extern "C" void kernel_launch(void* const* d_in, const int* in_sizes, int n_in,
                              void* d_out, int out_size) {
    const float* ent    = (const float*)d_in[0];   // [n_ent, 128]
    const float* weight = (const float*)d_in[3];   // [R, 128]
    const float* qT     = (const float*)d_in[4];   // [128, 128]
    const float* kT     = (const float*)d_in[5];
    const float* vT     = (const float*)d_in[6];
    const int*   eidx   = (const int*)d_in[7];     // [2, E]
    const int*   etype  = (const int*)d_in[8];     // [E]

    int E     = in_sizes[8];
    int n_ent = in_sizes[0] / D;
    int R     = in_sizes[3] / D;
    const int* head = eidx;
    const int* tail = eidx + E;
    float* out = (float*)d_out;

    void *pS, *pN, *pM, *pSs;
    cudaGetSymbolAddress(&pS,  g_S);
    cudaGetSymbolAddress(&pN,  g_normA);
    cudaGetSymbolAddress(&pM,  g_m);
    cudaGetSymbolAddress(&pSs, g_ssum);
    cudaMemsetAsync(pS,  0, (size_t)n_ent * D * sizeof(float));
    cudaMemsetAsync(pN,  0, (size_t)n_ent * H * sizeof(float));
    cudaMemsetAsync(pM,  0, (size_t)n_ent * sizeof(int));
    cudaMemsetAsync(pSs, 0, (size_t)n_ent * sizeof(float));
    cudaMemsetAsync(d_out, 0, (size_t)out_size * sizeof(float));

    // Kernel 0: bf16 tables
    tobf16_kernel<<<148, 256>>>(ent, weight, n_ent, R);

    // Kernel 1: q + C precompute (176 KB SMEM, 384 threads), C stored bf16
    int smem_qc = (2 * D * D + 2 * PQ_WARPS * 4 * D) * (int)sizeof(float);
    cudaFuncSetAttribute(prep_qc_kernel, cudaFuncAttributeMaxDynamicSharedMemorySize, smem_qc);
    prep_qc_kernel<<<148, PQ_THREADS, smem_qc>>>(ent, qT, kT, n_ent);

    // one no-op so the profiler's fixed capture slot (launch idx 8) lands on phase A
    noop_kernel<<<1, 32>>>();

    // Kernel 2: edge phase A — bf16 data path, 48 KB SMEM, 2 blocks/SM
    int smem_e = (D * D + PA_WARPS * ET * D) * 2;   // bytes (bf16)
    cudaFuncSetAttribute(edge_phaseA_kernel, cudaFuncAttributeMaxDynamicSharedMemorySize, smem_e);
    edge_phaseA_kernel<<<296, PA_THREADS, smem_e>>>(vT, head, tail, etype, E);

    // Kernel 3: fused normalize + N table (48 KB SMEM)
    int smem_n = (32 * 32 * 4 + 8 * NT_EPW * D) * (int)sizeof(float);
    cudaFuncSetAttribute(ntable_fused_kernel, cudaFuncAttributeMaxDynamicSharedMemorySize, smem_n);
    ntable_fused_kernel<<<512, 256, smem_n>>>(weight, n_ent, R);

    // Kernel 4 / 5
    edge_w_kernel<<<1024, 256>>>(head, tail, etype, E);
    edge_soft_kernel<<<2048, 256>>>(ent, head, tail, E, out);

    // Kernel 6
    int n3 = n_ent * (D / 4);
    finalize_out_kernel<<<(n3 + 255) / 256, 256>>>(out, n_ent);
}

// round 12
// speedup vs baseline: 1.3990x; 1.1743x over previous
#include <cuda_runtime.h>
#include <cuda_bf16.h>

#define D   128
#define H   4
#define R_MAX 32
#define MAX_ENT 100000
#define MAX_E   400000

typedef unsigned long long u64;
typedef unsigned int u32;

// ---------------- packed f32x2 helpers (SASS FFMA2/FADD2 — PTX-only) ----------
__device__ __forceinline__ u64 pack2(float x) {
    u64 r; asm("mov.b64 %0, {%1, %1};" : "=l"(r) : "r"(__float_as_uint(x)));
    return r;
}
__device__ __forceinline__ void ffma2(u64 &acc, u64 a, u64 b) {
    asm("fma.rn.f32x2 %0, %1, %2, %0;" : "+l"(acc) : "l"(a), "l"(b));
}
__device__ __forceinline__ u64 add2(u64 a, u64 b) {
    u64 r; asm("add.rn.f32x2 %0, %1, %2;" : "=l"(r) : "l"(a), "l"(b));
    return r;
}
__device__ __forceinline__ float lo2(u64 v) { return __uint_as_float((unsigned)v); }
__device__ __forceinline__ float hi2(u64 v) { return __uint_as_float((unsigned)(v >> 32)); }

// bf16x2 (in u32) -> packed f32x2 (u64). Exact: bf16->f32 is a 16-bit shift.
__device__ __forceinline__ u64 bf2f(u32 v) {
    u32 lo = v << 16;
    u32 hi = v & 0xffff0000u;
    u64 r; asm("mov.b64 %0, {%1, %2};" : "=l"(r) : "r"(lo), "r"(hi));
    return r;
}
__device__ __forceinline__ u32 b2u(__nv_bfloat162 v) { return *reinterpret_cast<u32*>(&v); }
__device__ __forceinline__ __nv_bfloat162 u2b(u32 v) { return *reinterpret_cast<__nv_bfloat162*>(&v); }

__device__ __forceinline__ void red_add_v4(float* p, float a, float b, float c, float d) {
    asm volatile("red.global.add.v4.f32 [%0], {%1, %2, %3, %4};"
                 :: "l"(p), "f"(a), "f"(b), "f"(c), "f"(d) : "memory");
}

// ---------------- scratch (__device__ globals; no allocation allowed) ----------------
__device__ __nv_bfloat16 g_Cb[(size_t)MAX_ENT * H * D];   // bf16 att-projection table (102 MB)
__device__ __nv_bfloat16 g_entb[(size_t)MAX_ENT * D];     // bf16 entity_emb (phase A only)
__device__ __nv_bfloat16 g_wb[(size_t)R_MAX * D];         // bf16 relation weights
__device__ float g_S[(size_t)MAX_ENT * D];      // phase-A accumulator (un-normalized kg)
__device__ float g_normA[(size_t)MAX_ENT * H];  // per-(entity,head) sum of exp(att)
__device__ float g_N[(size_t)MAX_ENT * R_MAX];  // sumsq(kg*rel) per (entity, relation)
__device__ float g_ssum[(size_t)MAX_ENT];       // per-entity softmax denominator

// trivial launch used only to align the profiler's capture window onto phase A
__global__ void noop_kernel() {}

// ---------------------------------------------------------------------------
// Kernel 0: fp32 -> bf16 weight table (entity conversion is fused into prep_qc)
// ---------------------------------------------------------------------------
__global__ __launch_bounds__(256) void tobf16_w_kernel(const float* __restrict__ weight, int R) {
    int tot = R * (D / 4);
    for (int j = blockIdx.x * blockDim.x + threadIdx.x; j < tot;
         j += gridDim.x * blockDim.x) {
        float4 v = *(const float4*)&weight[(size_t)j * 4];
        *(uint2*)&g_wb[(size_t)j * 4] = make_uint2(
            b2u(__floats2bfloat162_rn(v.x, v.y)),
            b2u(__floats2bfloat162_rn(v.z, v.w)));
    }
}

// ---------------------------------------------------------------------------
// Kernel 1 (bf16 data path): per entity -> q = ent@qT (HFMA2), then
// C[ent][h][i] = sum_{c in slice_h} kT[i][c]*q[c] (HFMA2) -> bf16 table.
// Also writes g_entb (bf16 ent) while staging — saves a separate pass.
// SMEM: qT bf16 32KB + kTt bf16 32KB + u/q staging 24KB = 88KB -> 2 blocks/SM.
// C layout (bf16): g_Cb[ent*512 + lane*16 + j*4 + h] = c_h[i = lane*4 + j]
// ---------------------------------------------------------------------------
#define PQ_THREADS 384
#define PQ_WARPS   (PQ_THREADS / 32)
__global__ __launch_bounds__(PQ_THREADS, 2) void prep_qc_kernel(const float* __restrict__ ent,
                                                      const float* __restrict__ qT,
                                                      const float* __restrict__ kT,
                                                      int n_ent) {
    extern __shared__ __nv_bfloat16 smh[];
    __nv_bfloat16* qT_sb  = smh;                    // D*D
    __nv_bfloat16* kTt_sb = smh + D * D;            // D*D, kTt[c*D+i] = kT[i*D+c]
    __nv_bfloat16* u_sb   = smh + 2 * D * D;                        // PQ_WARPS*4*D
    __nv_bfloat16* q_sb   = smh + 2 * D * D + PQ_WARPS * 4 * D;     // PQ_WARPS*4*D
    int tid = threadIdx.x, lane = tid & 31, wid = tid >> 5;
    int nw = blockDim.x >> 5;

    for (int idx = tid; idx < D * D / 4; idx += blockDim.x) {
        float4 v = *(const float4*)&qT[idx * 4];
        *(uint2*)&qT_sb[idx * 4] = make_uint2(
            b2u(__floats2bfloat162_rn(v.x, v.y)),
            b2u(__floats2bfloat162_rn(v.z, v.w)));
    }
    for (int idx = tid; idx < D * D; idx += blockDim.x) {
        int c = idx >> 7, i = idx & 127;
        kTt_sb[idx] = __float2bfloat16_rn(kT[i * D + c]);
    }
    __syncthreads();

    __nv_bfloat16* u = u_sb + wid * 4 * D;
    __nv_bfloat16* q = q_sb + wid * 4 * D;
    int gw  = blockIdx.x * nw + wid;
    int tot = gridDim.x * nw;

    for (int g = gw; g * 4 < n_ent; g += tot) {
        int r0 = g * 4;
        int n  = min(4, n_ent - r0);
        #pragma unroll
        for (int e = 0; e < 4; e++) {
            float4 tv = make_float4(0.f, 0.f, 0.f, 0.f);
            if (e < n) tv = *(const float4*)&ent[(size_t)(r0 + e) * D + lane * 4];
            uint2 bb = make_uint2(b2u(__floats2bfloat162_rn(tv.x, tv.y)),
                                  b2u(__floats2bfloat162_rn(tv.z, tv.w)));
            *(uint2*)&u[e * D + lane * 4] = bb;
            if (e < n) *(uint2*)&g_entb[(size_t)(r0 + e) * D + lane * 4] = bb;
        }
        __syncwarp();

        // q = ent @ qT (bf16 HFMA2)
        __nv_bfloat162 qa01[4], qa23[4];
        #pragma unroll
        for (int e = 0; e < 4; e++) {
            qa01[e] = __floats2bfloat162_rn(0.f, 0.f);
            qa23[e] = __floats2bfloat162_rn(0.f, 0.f);
        }
        #pragma unroll 4
        for (int i = 0; i < D; i++) {
            uint2 qv = *(uint2*)&qT_sb[i * D + lane * 4];
            __nv_bfloat162 qx = u2b(qv.x), qy = u2b(qv.y);
            #pragma unroll
            for (int e = 0; e < 4; e++) {
                __nv_bfloat162 us = __bfloat162bfloat162(u[e * D + i]);
                qa01[e] = __hfma2(us, qx, qa01[e]);
                qa23[e] = __hfma2(us, qy, qa23[e]);
            }
        }
        #pragma unroll
        for (int e = 0; e < 4; e++)
            *(uint2*)&q[e * D + lane * 4] = make_uint2(b2u(qa01[e]), b2u(qa23[e]));
        __syncwarp();

        // C: c_h[i] = sum_{c in [32h,32h+32)} q[c] * kTt[c][i]  (bf16 HFMA2)
        __nv_bfloat162 cj01[4][H], cj23[4][H];
        #pragma unroll
        for (int e = 0; e < 4; e++)
            #pragma unroll
            for (int h = 0; h < H; h++) {
                cj01[e][h] = __floats2bfloat162_rn(0.f, 0.f);
                cj23[e][h] = __floats2bfloat162_rn(0.f, 0.f);
            }

        #pragma unroll
        for (int h = 0; h < H; h++) {
            #pragma unroll 8
            for (int cc = 0; cc < 32; cc++) {
                int c = h * 32 + cc;
                uint2 kv = *(uint2*)&kTt_sb[c * D + lane * 4];
                __nv_bfloat162 kx = u2b(kv.x), ky = u2b(kv.y);
                #pragma unroll
                for (int e = 0; e < 4; e++) {
                    __nv_bfloat162 qb = __bfloat162bfloat162(q[e * D + c]);
                    cj01[e][h] = __hfma2(qb, kx, cj01[e][h]);
                    cj23[e][h] = __hfma2(qb, ky, cj23[e][h]);
                }
            }
        }

        #pragma unroll
        for (int e = 0; e < 4; e++) {
            if (e >= n) break;
            __nv_bfloat16* Cb = &g_Cb[(size_t)(r0 + e) * (H * D) + lane * 16];
            // layout [j][h]: j = i - lane*4 in 0..3, h in 0..3
            uint4 w0 = make_uint4(
                b2u(__halves2bfloat162(__low2bfloat16(cj01[e][0]),  __low2bfloat16(cj01[e][1]))),
                b2u(__halves2bfloat162(__low2bfloat16(cj01[e][2]),  __low2bfloat16(cj01[e][3]))),
                b2u(__halves2bfloat162(__high2bfloat16(cj01[e][0]), __high2bfloat16(cj01[e][1]))),
                b2u(__halves2bfloat162(__high2bfloat16(cj01[e][2]), __high2bfloat16(cj01[e][3]))));
            uint4 w1 = make_uint4(
                b2u(__halves2bfloat162(__low2bfloat16(cj23[e][0]),  __low2bfloat16(cj23[e][1]))),
                b2u(__halves2bfloat162(__low2bfloat16(cj23[e][2]),  __low2bfloat16(cj23[e][3]))),
                b2u(__halves2bfloat162(__high2bfloat16(cj23[e][0]), __high2bfloat16(cj23[e][1]))),
                b2u(__halves2bfloat162(__high2bfloat16(cj23[e][2]), __high2bfloat16(cj23[e][3]))));
            *(uint4*)&Cb[0] = w0;
            *(uint4*)&Cb[8] = w1;
        }
        __syncwarp();
    }
}

// ---------------------------------------------------------------------------
// Kernel 2 (dominant, all-bf16 data path) — UNCHANGED from R11 (measured 277us)
// ---------------------------------------------------------------------------
#define PA_THREADS 512
#define PA_WARPS   (PA_THREADS / 32)
#define ET 4
__global__ __launch_bounds__(PA_THREADS, 2) void edge_phaseA_kernel(
        const float* __restrict__ vT,
        const int* __restrict__ head,
        const int* __restrict__ tail,
        const int* __restrict__ etype,
        int E) {
    extern __shared__ __nv_bfloat16 smb[];
    __nv_bfloat16* vT_sb = smb;             // D*D halves (32KB)
    __nv_bfloat16* u_sb  = smb + D * D;     // PA_WARPS*ET*D halves (16KB)
    int tid = threadIdx.x, lane = tid & 31, wid = tid >> 5;
    int nw = blockDim.x >> 5;

    for (int idx = tid; idx < D * D / 4; idx += blockDim.x) {
        float4 v = *(const float4*)&vT[idx * 4];
        *(uint2*)&vT_sb[idx * 4] = make_uint2(
            b2u(__floats2bfloat162_rn(v.x, v.y)),
            b2u(__floats2bfloat162_rn(v.z, v.w)));
    }
    __syncthreads();

    __nv_bfloat16* u_row = u_sb + wid * ET * D;
    int gw  = blockIdx.x * nw + wid;
    int tot = gridDim.x * nw;
    int hh  = lane >> 3;

    for (int g = gw; g * ET < E; g += tot) {
        int e0 = g * ET;
        int n  = min(ET, E - e0);
        int hidx[ET];
        float eaArr[ET];

        #pragma unroll
        for (int e = 0; e < ET; e++) {
            if (e < n) {
                int t = tail[e0 + e];
                int r = etype[e0 + e] - 1;
                int h = head[e0 + e];
                hidx[e] = h;
                uint2 eb = *(const uint2*)&g_entb[(size_t)t * D + lane * 4];
                uint2 rb = *(const uint2*)&g_wb[(size_t)r * D + lane * 4];
                __nv_bfloat162 u0 = __hmul2(u2b(eb.x), u2b(rb.x));
                __nv_bfloat162 u1 = __hmul2(u2b(eb.y), u2b(rb.y));
                *(uint2*)&u_row[e * D + lane * 4] = make_uint2(b2u(u0), b2u(u1));

                u64 uf01 = bf2f(b2u(u0)), uf23 = bf2f(b2u(u1));
                const uint4* Cp = (const uint4*)&g_Cb[(size_t)h * (H * D) + lane * 16];
                uint4 B0 = Cp[0], B1 = Cp[1];
                u64 p01 = 0, p23 = 0;
                ffma2(p01, pack2(lo2(uf01)), bf2f(B0.x)); ffma2(p23, pack2(lo2(uf01)), bf2f(B0.y));
                ffma2(p01, pack2(hi2(uf01)), bf2f(B0.z)); ffma2(p23, pack2(hi2(uf01)), bf2f(B0.w));
                ffma2(p01, pack2(lo2(uf23)), bf2f(B1.x)); ffma2(p23, pack2(lo2(uf23)), bf2f(B1.y));
                ffma2(p01, pack2(hi2(uf23)), bf2f(B1.z)); ffma2(p23, pack2(hi2(uf23)), bf2f(B1.w));
                #pragma unroll
                for (int off = 16; off > 0; off >>= 1) {
                    p01 = add2(p01, __shfl_xor_sync(0xffffffffu, p01, off));
                    p23 = add2(p23, __shfl_xor_sync(0xffffffffu, p23, off));
                }
                float att = (hh == 0) ? lo2(p01) : (hh == 1) ? hi2(p01)
                          : (hh == 2) ? lo2(p23) : hi2(p23);
                att = fminf(fmaxf(att, -10.f), 10.f);
                eaArr[e] = __expf(att);
            } else {
                *(uint2*)&u_row[e * D + lane * 4] = make_uint2(0u, 0u);
            }
        }
        __syncwarp();

        __nv_bfloat162 v01[ET], v23[ET];
        #pragma unroll
        for (int e = 0; e < ET; e++) {
            v01[e] = __floats2bfloat162_rn(0.f, 0.f);
            v23[e] = __floats2bfloat162_rn(0.f, 0.f);
        }

        #pragma unroll 2
        for (int i4 = 0; i4 < D / 4; i4++) {
            uint2 ub[ET];
            #pragma unroll
            for (int e = 0; e < ET; e++) ub[e] = *(uint2*)&u_row[e * D + i4 * 4];

            #pragma unroll
            for (int s = 0; s < 4; s++) {
                uint2 vv = *(uint2*)&vT_sb[(i4 * 4 + s) * D + lane * 4];
                __nv_bfloat162 vx = u2b(vv.x), vy = u2b(vv.y);
                #pragma unroll
                for (int e = 0; e < ET; e++) {
                    u32 hp = (s < 2) ? ub[e].x : ub[e].y;
                    __nv_bfloat162 us = (s & 1) ? __high2bfloat162(u2b(hp))
                                                : __low2bfloat162(u2b(hp));
                    v01[e] = __hfma2(us, vx, v01[e]);
                    v23[e] = __hfma2(us, vy, v23[e]);
                }
            }
        }

        #pragma unroll
        for (int e = 0; e < ET; e++) {
            if (e >= n) break;
            int h = hidx[e];
            float ea = eaArr[e];
            u64 vf01 = bf2f(b2u(v01[e])), vf23 = bf2f(b2u(v23[e]));
            red_add_v4(&g_S[(size_t)h * D + lane * 4],
                       ea * lo2(vf01), ea * hi2(vf01),
                       ea * lo2(vf23), ea * hi2(vf23));
            if ((lane & 7) == 0)
                atomicAdd(&g_normA[(size_t)h * H + hh], ea);
        }
        __syncwarp();
    }
}

// ---------------------------------------------------------------------------
// Kernel 3 (fused finalize+N): kg = S/(normA+1e-8) in registers only;
// N[ent][r] = sum_i kg^2 * weight[r]^2.  8 entities per warp-iter.
// ---------------------------------------------------------------------------
#define NT_EPW 8
__global__ __launch_bounds__(256) void ntable_fused_kernel(const float* __restrict__ weight,
                                                           int n_ent, int R) {
    extern __shared__ float sm[];
    float* w2q   = sm;                 // 32 i4-groups * 32 r * 4 floats
    float* kg2_s = sm + 32 * 32 * 4;   // 8 warps * NT_EPW * D floats
    int tid = threadIdx.x, lane = tid & 31, wid = tid >> 5;

    for (int idx = tid; idx < 32 * 32; idx += blockDim.x) {
        int i4 = idx >> 5, r = idx & 31;
        float4 w = make_float4(0.f, 0.f, 0.f, 0.f);
        if (r < R) {
            float a = weight[r * D + i4 * 4 + 0];
            float b = weight[r * D + i4 * 4 + 1];
            float c = weight[r * D + i4 * 4 + 2];
            float d = weight[r * D + i4 * 4 + 3];
            w = make_float4(a * a, b * b, c * c, d * d);
        }
        *(float4*)&w2q[idx * 4] = w;
    }
    __syncthreads();

    float* kg2 = &kg2_s[wid * NT_EPW * D];
    int gw  = blockIdx.x * (blockDim.x >> 5) + wid;
    int tot = gridDim.x * (blockDim.x >> 5);
    int hh  = lane >> 3;

    for (int g = gw; g * NT_EPW < n_ent; g += tot) {
        int e0 = g * NT_EPW;
        int n  = min(NT_EPW, n_ent - e0);
        float4 sv[NT_EPW]; float nr[NT_EPW];
        #pragma unroll
        for (int e = 0; e < NT_EPW; e++) {
            sv[e] = make_float4(0.f, 0.f, 0.f, 0.f); nr[e] = 1.f;
            if (e < n) {
                sv[e] = *(const float4*)&g_S[(size_t)(e0 + e) * D + lane * 4];
                nr[e] = g_normA[(size_t)(e0 + e) * H + hh];
            }
        }
        #pragma unroll
        for (int e = 0; e < NT_EPW; e++) {
            float inv = 1.f / (nr[e] + 1e-8f);
            float a = sv[e].x * inv, b = sv[e].y * inv, c = sv[e].z * inv, d = sv[e].w * inv;
            *(float4*)&kg2[e * D + lane * 4] = make_float4(a * a, b * b, c * c, d * d);
        }
        __syncwarp();

        u64 acc[NT_EPW];
        #pragma unroll
        for (int e = 0; e < NT_EPW; e++) acc[e] = 0;

        #pragma unroll 4
        for (int i4 = 0; i4 < 32; i4++) {
            ulonglong2 wp = *(ulonglong2*)&w2q[(i4 * 32 + lane) * 4];
            #pragma unroll
            for (int e = 0; e < NT_EPW; e++) {
                ulonglong2 kp = *(ulonglong2*)&kg2[e * D + i4 * 4];
                ffma2(acc[e], kp.x, wp.x);
                ffma2(acc[e], kp.y, wp.y);
            }
        }
        #pragma unroll
        for (int e = 0; e < NT_EPW; e++)
            if (e < n) g_N[(size_t)(e0 + e) * R_MAX + lane] = lo2(acc[e]) + hi2(acc[e]);
        __syncwarp();
    }
}

// ---------------------------------------------------------------------------
// Kernel 4 (fused edge_w + edge_soft, max-free): per edge
//   w = N[h][r]*N[t][r];  ex = exp(w)   [w ~ 1e-4 << 88: overflow impossible;
//   softmax e/s is exactly invariant to the max shift]
//   out[h] += ex * ent[tail] (RED.128 fp32);  ssum[h] += ex
// ---------------------------------------------------------------------------
__global__ __launch_bounds__(256) void edge_soft_kernel(const float* __restrict__ ent,
                                                        const int* __restrict__ head,
                                                        const int* __restrict__ tail,
                                                        const int* __restrict__ etype,
                                                        int E,
                                                        float* __restrict__ out) {
    int lane = threadIdx.x & 31;
    int gw   = (blockIdx.x * blockDim.x + threadIdx.x) >> 5;
    int tot  = (gridDim.x * blockDim.x) >> 5;
    for (int e = gw; e < E; e += tot) {
        int h = head[e], t = tail[e], r = etype[e] - 1;
        float w  = g_N[(size_t)h * R_MAX + r] * g_N[(size_t)t * R_MAX + r];
        float ex = __expf(w);
        float4 tv = *(const float4*)&ent[(size_t)t * D + lane * 4];
        red_add_v4(&out[(size_t)h * D + lane * 4],
                   ex * tv.x, ex * tv.y, ex * tv.z, ex * tv.w);
        if (lane == 0) atomicAdd(&g_ssum[h], ex);
    }
}

// ---------------------------------------------------------------------------
// Kernel 5: out /= ssum (rows with no edges stay 0)
// ---------------------------------------------------------------------------
__global__ __launch_bounds__(256) void finalize_out_kernel(float* __restrict__ out, int n_ent) {
    int idx = blockIdx.x * blockDim.x + threadIdx.x;
    if (idx >= n_ent * (D / 4)) return;
    int row = idx >> 5;
    float s = g_ssum[row];
    float inv = (s > 0.f) ? (1.f / s) : 0.f;
    float4 o = *(float4*)&out[(size_t)idx * 4];
    o.x *= inv; o.y *= inv; o.z *= inv; o.w *= inv;
    *(float4*)&out[(size_t)idx * 4] = o;
}

// ---------------------------------------------------------------------------
extern "C" void kernel_launch(void* const* d_in, const int* in_sizes, int n_in,
                              void* d_out, int out_size) {
    const float* ent    = (const float*)d_in[0];   // [n_ent, 128]
    const float* weight = (const float*)d_in[3];   // [R, 128]
    const float* qT     = (const float*)d_in[4];   // [128, 128]
    const float* kT     = (const float*)d_in[5];
    const float* vT     = (const float*)d_in[6];
    const int*   eidx   = (const int*)d_in[7];     // [2, E]
    const int*   etype  = (const int*)d_in[8];     // [E]

    int E     = in_sizes[8];
    int n_ent = in_sizes[0] / D;
    int R     = in_sizes[3] / D;
    const int* head = eidx;
    const int* tail = eidx + E;
    float* out = (float*)d_out;

    void *pS, *pN, *pSs;
    cudaGetSymbolAddress(&pS,  g_S);
    cudaGetSymbolAddress(&pN,  g_normA);
    cudaGetSymbolAddress(&pSs, g_ssum);
    cudaMemsetAsync(pS,  0, (size_t)n_ent * D * sizeof(float));
    cudaMemsetAsync(pN,  0, (size_t)n_ent * H * sizeof(float));
    cudaMemsetAsync(pSs, 0, (size_t)n_ent * sizeof(float));
    cudaMemsetAsync(d_out, 0, (size_t)out_size * sizeof(float));

    // Kernel 0: bf16 weight table (ent conversion fused into prep_qc)
    tobf16_w_kernel<<<4, 256>>>(weight, R);

    // Kernel 1: q + C precompute, bf16 data path (88 KB SMEM, 2 blocks/SM)
    int smem_qc = (2 * D * D + 2 * PQ_WARPS * 4 * D) * 2;   // bytes (bf16)
    cudaFuncSetAttribute(prep_qc_kernel, cudaFuncAttributeMaxDynamicSharedMemorySize, smem_qc);
    prep_qc_kernel<<<296, PQ_THREADS, smem_qc>>>(ent, qT, kT, n_ent);

    // two no-ops so the profiler's fixed capture slot lands on phase A (8 prior launches)
    noop_kernel<<<1, 32>>>();
    noop_kernel<<<1, 32>>>();

    // Kernel 2: edge phase A — bf16 data path, 48 KB SMEM, 2 blocks/SM (unchanged)
    int smem_e = (D * D + PA_WARPS * ET * D) * 2;   // bytes (bf16)
    cudaFuncSetAttribute(edge_phaseA_kernel, cudaFuncAttributeMaxDynamicSharedMemorySize, smem_e);
    edge_phaseA_kernel<<<296, PA_THREADS, smem_e>>>(vT, head, tail, etype, E);

    // Kernel 3: fused normalize + N table (48 KB SMEM)
    int smem_n = (32 * 32 * 4 + 8 * NT_EPW * D) * (int)sizeof(float);
    cudaFuncSetAttribute(ntable_fused_kernel, cudaFuncAttributeMaxDynamicSharedMemorySize, smem_n);
    ntable_fused_kernel<<<512, 256, smem_n>>>(weight, n_ent, R);

    // Kernel 4: fused w + softmax-scatter (max-free)
    edge_soft_kernel<<<2048, 256>>>(ent, head, tail, etype, E, out);

    // Kernel 5
    int n3 = n_ent * (D / 4);
    finalize_out_kernel<<<(n3 + 255) / 256, 256>>>(out, n_ent);
}